// round 1
// baseline (speedup 1.0000x reference)
#include <cuda_runtime.h>
#include <cstdint>
#include <math.h>

// Problem constants (fixed by the dataset)
#define GG 8
#define MM 1024
#define NN 8192          // GG*MM
#define HH 256
#define NHEADS 8
#define HDIM 32
#define FFND 1024
#define QKVD 768

// ---------------- scratch (device globals; no allocation) ----------------
__device__ float    g_deg [NN];
__device__ float    g_dinv[NN];
__device__ float    g_xw  [NN * HH];
__device__ float    g_xl  [NN * HH];
__device__ uint32_t g_adj [GG * MM * 32];
__device__ unsigned char g_dist[(size_t)GG * MM * MM];   // 8 MB
__device__ float    g_qkv [(size_t)NN * QKVD];
__device__ float    g_attn[NN * HH];
__device__ float    g_tmp [NN * HH];
__device__ float    g_h1  [NN * HH];
__device__ float    g_mid [(size_t)NN * FFND];
__device__ float    g_h2  [NN * HH];
__device__ float    g_y   [NN * HH];

// ---------------- utility fills ----------------
__global__ void fill_f(float* p, float v, int n) {
    int i = blockIdx.x * blockDim.x + threadIdx.x;
    if (i < n) p[i] = v;
}
__global__ void fill_u(uint32_t* p, uint32_t v, int n) {
    int i = blockIdx.x * blockDim.x + threadIdx.x;
    if (i < n) p[i] = v;
}

// ---------------- GCN pieces ----------------
__global__ void deg_kernel(const int* __restrict__ ei, int E, float* __restrict__ deg) {
    int e = blockIdx.x * blockDim.x + threadIdx.x;
    if (e < E) atomicAdd(&deg[ei[E + e]], 1.0f);
}
__global__ void dinv_kernel(const float* __restrict__ deg, float* __restrict__ dinv) {
    int i = blockIdx.x * blockDim.x + threadIdx.x;
    if (i < NN) dinv[i] = rsqrtf(deg[i] + 1.0f);   // +1 self loop
}
__global__ void xlocal_init(const float* __restrict__ xw, const float* __restrict__ dinv,
                            const float* __restrict__ gcn_b, float* __restrict__ xl) {
    int idx = blockIdx.x * blockDim.x + threadIdx.x;  // over NN*HH
    int i = idx >> 8, c = idx & 255;
    float di = dinv[i];
    xl[idx] = xw[idx] * di * di + gcn_b[c];
}
__global__ void edge_scatter(const int* __restrict__ ei, int E,
                             const float* __restrict__ xw, const float* __restrict__ dinv,
                             float* __restrict__ xl) {
    int idx = blockIdx.x * blockDim.x + threadIdx.x;   // E*64 threads
    int e  = idx >> 6;
    int c4 = (idx & 63) * 4;
    if (e >= E) return;
    int s = __ldg(&ei[e]);
    int d = __ldg(&ei[E + e]);
    float w = __ldg(&dinv[s]) * __ldg(&dinv[d]);
    const float4 v = *(const float4*)&xw[(size_t)s * HH + c4];
    float* dst = &xl[(size_t)d * HH + c4];
    atomicAdd(dst + 0, v.x * w);
    atomicAdd(dst + 1, v.y * w);
    atomicAdd(dst + 2, v.z * w);
    atomicAdd(dst + 3, v.w * w);
}

// ---------------- SPD: adjacency bitsets + bitset BFS ----------------
__global__ void adj_kernel(const int* __restrict__ ei, int E, uint32_t* __restrict__ adj) {
    int e = blockIdx.x * blockDim.x + threadIdx.x;
    if (e >= E) return;
    int s = ei[e], d = ei[E + e];
    if (s == d || (s >> 10) != (d >> 10)) return;
    int g = s >> 10, ls = s & 1023, ld = d & 1023;
    atomicOr(&adj[((size_t)g * MM + ls) * 32 + (ld >> 5)], 1u << (ld & 31));
    atomicOr(&adj[((size_t)g * MM + ld) * 32 + (ls >> 5)], 1u << (ls & 31));
}

// grid 64 blocks (8 per graph), 128 threads; each thread owns one source row.
__launch_bounds__(128)
__global__ void spd_kernel(const uint32_t* __restrict__ adj, unsigned char* __restrict__ dist) {
    extern __shared__ uint32_t adj_sh[];   // [1024][33] padded
    int g = blockIdx.x >> 3;
    const uint32_t* ga = adj + (size_t)g * MM * 32;
    for (int idx = threadIdx.x; idx < MM * 32; idx += blockDim.x) {
        int r = idx >> 5, w = idx & 31;
        adj_sh[r * 33 + w] = ga[idx];
    }
    __syncthreads();

    int i = (blockIdx.x & 7) * 128 + threadIdx.x;
    unsigned char* drow = dist + ((size_t)g * MM + i) * MM;

    uint32_t reach[32], frontier[32];
#pragma unroll
    for (int w = 0; w < 32; ++w) {
        uint32_t a = adj_sh[i * 33 + w];
        reach[w] = a; frontier[w] = a;
    }
    // write d=1 / default 6 for full row
#pragma unroll
    for (int w = 0; w < 32; ++w) {
        uint32_t f = frontier[w];
        uint32_t* dp = (uint32_t*)(drow + w * 32);
#pragma unroll
        for (int q = 0; q < 8; ++q) {
            uint32_t nib = (f >> (q * 4)) & 0xF;
            uint32_t word = 0x06060606u;
            if (nib & 1) word = (word & 0xFFFFFF00u) | 0x01u;
            if (nib & 2) word = (word & 0xFFFF00FFu) | 0x0100u;
            if (nib & 4) word = (word & 0xFF00FFFFu) | 0x010000u;
            if (nib & 8) word = (word & 0x00FFFFFFu) | 0x01000000u;
            dp[q] = word;
        }
    }
    drow[i] = 0;                         // diagonal
    reach[i >> 5] |= 1u << (i & 31);     // keep diag out of future frontiers

    for (int d = 2; d <= 5; ++d) {
        uint32_t nw[32];
#pragma unroll
        for (int w = 0; w < 32; ++w) nw[w] = 0u;
        for (int w = 0; w < 32; ++w) {
            uint32_t f = frontier[w];
            while (f) {
                int b = __ffs((int)f) - 1;
                f &= f - 1;
                const uint32_t* aj = &adj_sh[(w * 32 + b) * 33];
#pragma unroll
                for (int ww = 0; ww < 32; ++ww) nw[ww] |= aj[ww];
            }
        }
        uint32_t any = 0;
        uint32_t rep = (uint32_t)d * 0x01010101u;
#pragma unroll
        for (int w = 0; w < 32; ++w) {
            uint32_t newly = nw[w] & ~reach[w];
            frontier[w] = newly;
            reach[w] |= newly;
            any |= newly;
            if (newly) {
                uint32_t* dp = (uint32_t*)(drow + w * 32);
#pragma unroll
                for (int q = 0; q < 8; ++q) {
                    uint32_t nib = (newly >> (q * 4)) & 0xF;
                    if (nib) {
                        uint32_t m = ((nib & 1) ? 0xFFu : 0u) | ((nib & 2) ? 0xFF00u : 0u)
                                   | ((nib & 4) ? 0xFF0000u : 0u) | ((nib & 8) ? 0xFF000000u : 0u);
                        dp[q] = (dp[q] & ~m) | (rep & m);
                    }
                }
            }
        }
        if (!any) break;
    }
}

// ---------------- generic fp32 tiled GEMM: C = A @ W^T (+bias)(+gelu)(+res) ----------------
// A:[rows,K] row-major, W:[F,K] row-major. Tiles 64x64x16, 256 threads, 4x4/thread.
template <int GELU, int RES>
__launch_bounds__(256)
__global__ void gemm_k(const float* __restrict__ A, const float* __restrict__ W,
                       const float* __restrict__ bias, const float* __restrict__ res,
                       float* __restrict__ C, int K, int F) {
    __shared__ float As[64][17];
    __shared__ float Ws[16][65];
    int m0 = blockIdx.x * 64, f0 = blockIdx.y * 64;
    int tid = threadIdx.x;
    int lk = tid & 15, lr = tid >> 4;
    int tx = tid & 15, ty = tid >> 4;
    float acc[4][4];
#pragma unroll
    for (int i = 0; i < 4; ++i)
#pragma unroll
        for (int j = 0; j < 4; ++j) acc[i][j] = 0.f;

    for (int k0 = 0; k0 < K; k0 += 16) {
#pragma unroll
        for (int p = 0; p < 4; ++p) {
            int r = lr + p * 16;
            As[r][lk]  = A[(size_t)(m0 + r) * K + k0 + lk];
            Ws[lk][r]  = W[(size_t)(f0 + r) * K + k0 + lk];
        }
        __syncthreads();
#pragma unroll
        for (int kk = 0; kk < 16; ++kk) {
            float a[4], b[4];
#pragma unroll
            for (int i = 0; i < 4; ++i) a[i] = As[ty * 4 + i][kk];
#pragma unroll
            for (int j = 0; j < 4; ++j) b[j] = Ws[kk][tx * 4 + j];
#pragma unroll
            for (int i = 0; i < 4; ++i)
#pragma unroll
                for (int j = 0; j < 4; ++j) acc[i][j] = fmaf(a[i], b[j], acc[i][j]);
        }
        __syncthreads();
    }
#pragma unroll
    for (int i = 0; i < 4; ++i) {
        int row = m0 + ty * 4 + i;
#pragma unroll
        for (int j = 0; j < 4; ++j) {
            int col = f0 + tx * 4 + j;
            float v = acc[i][j];
            if (bias) v += bias[col];
            if (GELU) v = v * normcdff(v);        // exact gelu
            if (RES)  v += res[(size_t)row * F + col];
            C[(size_t)row * F + col] = v;
        }
    }
}

// ---------------- fused attention (online softmax), 1 thread = 1 query row ----------------
__launch_bounds__(128)
__global__ void attn_kernel(const float* __restrict__ qkv, const unsigned char* __restrict__ dist,
                            const float* __restrict__ bias_emb, float* __restrict__ out) {
    __shared__ float Ks[128][36];
    __shared__ float Vs[128][36];
    __shared__ float btab[8];
    int gh = blockIdx.x;
    int g = gh >> 3, h = gh & 7;
    int i = blockIdx.y * 128 + threadIdx.x;
    if (threadIdx.x < 7) btab[threadIdx.x] = bias_emb[threadIdx.x];

    const float* qp = qkv + ((size_t)(g * MM + i)) * QKVD + h * HDIM;
    float q[32];
#pragma unroll
    for (int d = 0; d < 32; d += 4) {
        float4 t = *(const float4*)(qp + d);
        q[d] = t.x; q[d + 1] = t.y; q[d + 2] = t.z; q[d + 3] = t.w;
    }
    float acc[32];
#pragma unroll
    for (int d = 0; d < 32; ++d) acc[d] = 0.f;
    float mx = -1e30f, l = 0.f;
    const unsigned char* drow = dist + ((size_t)(g * MM + i)) * MM;
    const float scale = 0.17677669529663687f;  // 1/sqrt(32)

    for (int j0 = 0; j0 < MM; j0 += 128) {
        const float* kp = qkv + ((size_t)(g * MM + j0 + threadIdx.x)) * QKVD + HH + h * HDIM;
        const float* vp = kp + HH;
#pragma unroll
        for (int d = 0; d < 32; d += 4) {
            *(float4*)&Ks[threadIdx.x][d] = *(const float4*)(kp + d);
            *(float4*)&Vs[threadIdx.x][d] = *(const float4*)(vp + d);
        }
        __syncthreads();

        for (int jj = 0; jj < 128; jj += 4) {
            uint32_t d4 = *(const uint32_t*)(drow + j0 + jj);
#pragma unroll
            for (int t = 0; t < 4; ++t) {
                int j = jj + t;
                float s0 = 0.f, s1 = 0.f, s2 = 0.f, s3 = 0.f;
#pragma unroll
                for (int d = 0; d < 32; d += 16) {
                    float4 k0 = *(const float4*)&Ks[j][d + 0];
                    float4 k1 = *(const float4*)&Ks[j][d + 4];
                    float4 k2 = *(const float4*)&Ks[j][d + 8];
                    float4 k3 = *(const float4*)&Ks[j][d + 12];
                    s0 = fmaf(q[d+0], k0.x, fmaf(q[d+1], k0.y, fmaf(q[d+2], k0.z, fmaf(q[d+3], k0.w, s0))));
                    s1 = fmaf(q[d+4], k1.x, fmaf(q[d+5], k1.y, fmaf(q[d+6], k1.z, fmaf(q[d+7], k1.w, s1))));
                    s2 = fmaf(q[d+8], k2.x, fmaf(q[d+9], k2.y, fmaf(q[d+10],k2.z, fmaf(q[d+11],k2.w, s2))));
                    s3 = fmaf(q[d+12],k3.x, fmaf(q[d+13],k3.y, fmaf(q[d+14],k3.z, fmaf(q[d+15],k3.w, s3))));
                }
                float s = (s0 + s1) + (s2 + s3);
                s = s * scale + btab[(d4 >> (8 * t)) & 0xFF];
                if (s > mx) {
                    float corr = __expf(mx - s);
                    mx = s;
                    l *= corr;
#pragma unroll
                    for (int d = 0; d < 32; ++d) acc[d] *= corr;
                }
                float p = __expf(s - mx);
                l += p;
#pragma unroll
                for (int d = 0; d < 32; d += 4) {
                    float4 v4 = *(const float4*)&Vs[j][d];
                    acc[d + 0] = fmaf(p, v4.x, acc[d + 0]);
                    acc[d + 1] = fmaf(p, v4.y, acc[d + 1]);
                    acc[d + 2] = fmaf(p, v4.z, acc[d + 2]);
                    acc[d + 3] = fmaf(p, v4.w, acc[d + 3]);
                }
            }
        }
        __syncthreads();
    }
    float inv = 1.f / l;
    float* op = out + ((size_t)(g * MM + i)) * HH + h * HDIM;
#pragma unroll
    for (int d = 0; d < 32; d += 4) {
        float4 o;
        o.x = acc[d] * inv; o.y = acc[d + 1] * inv; o.z = acc[d + 2] * inv; o.w = acc[d + 3] * inv;
        *(float4*)(op + d) = o;
    }
}

// ---------------- LayerNorm (up to 3 summed inputs), one block per row ----------------
__launch_bounds__(256)
__global__ void ln_kernel(const float* __restrict__ a, const float* __restrict__ b,
                          const float* __restrict__ c, const float* __restrict__ gam,
                          const float* __restrict__ bet, float* __restrict__ out) {
    int row = blockIdx.x, t = threadIdx.x;
    size_t idx = (size_t)row * HH + t;
    float v = a[idx];
    if (b) v += b[idx];
    if (c) v += c[idx];
    float s = v, s2 = v * v;
#pragma unroll
    for (int o = 16; o; o >>= 1) {
        s  += __shfl_xor_sync(0xFFFFFFFFu, s, o);
        s2 += __shfl_xor_sync(0xFFFFFFFFu, s2, o);
    }
    __shared__ float sh1[8], sh2[8];
    int w = t >> 5, ln = t & 31;
    if (ln == 0) { sh1[w] = s; sh2[w] = s2; }
    __syncthreads();
    if (w == 0) {
        s  = (ln < 8) ? sh1[ln] : 0.f;
        s2 = (ln < 8) ? sh2[ln] : 0.f;
#pragma unroll
        for (int o = 4; o; o >>= 1) {
            s  += __shfl_xor_sync(0xFFFFFFFFu, s, o);
            s2 += __shfl_xor_sync(0xFFFFFFFFu, s2, o);
        }
        if (ln == 0) { sh1[0] = s; sh2[0] = s2; }
    }
    __syncthreads();
    float mean = sh1[0] * (1.f / HH);
    float var  = sh2[0] * (1.f / HH) - mean * mean;
    out[idx] = (v - mean) * rsqrtf(var + 1e-5f) * gam[t] + bet[t];
}

// ---------------- host ----------------
static void* sym(const void* s) { void* p = nullptr; cudaGetSymbolAddress(&p, s); return p; }

extern "C" void kernel_launch(void* const* d_in, const int* in_sizes, int n_in,
                              void* d_out, int out_size) {
    const float* x      = (const float*)d_in[0];
    const float* gcn_w  = (const float*)d_in[1];
    const float* gcn_b  = (const float*)d_in[2];
    const float* qkv_w  = (const float*)d_in[3];
    const float* qkv_b  = (const float*)d_in[4];
    const float* proj_w = (const float*)d_in[5];
    const float* proj_b = (const float*)d_in[6];
    const float* ln1_g  = (const float*)d_in[7];
    const float* ln1_b  = (const float*)d_in[8];
    const float* ln2_g  = (const float*)d_in[9];
    const float* ln2_b  = (const float*)d_in[10];
    const float* ffn1_w = (const float*)d_in[11];
    const float* ffn1_b = (const float*)d_in[12];
    const float* ffn2_w = (const float*)d_in[13];
    const float* ffn2_b = (const float*)d_in[14];
    const float* bias_e = (const float*)d_in[15];
    const float* oln1_g = (const float*)d_in[16];
    const float* oln1_b = (const float*)d_in[17];
    const float* oln2_g = (const float*)d_in[18];
    const float* oln2_b = (const float*)d_in[19];
    const float* offn1_w= (const float*)d_in[20];
    const float* offn1_b= (const float*)d_in[21];
    const float* offn2_w= (const float*)d_in[22];
    const float* offn2_b= (const float*)d_in[23];
    const int*   ei     = (const int*)d_in[24];
    int E = in_sizes[24] / 2;

    float*    p_deg  = (float*)sym(g_deg);
    float*    p_dinv = (float*)sym(g_dinv);
    float*    p_xw   = (float*)sym(g_xw);
    float*    p_xl   = (float*)sym(g_xl);
    uint32_t* p_adj  = (uint32_t*)sym(g_adj);
    unsigned char* p_dist = (unsigned char*)sym(g_dist);
    float*    p_qkv  = (float*)sym(g_qkv);
    float*    p_attn = (float*)sym(g_attn);
    float*    p_tmp  = (float*)sym(g_tmp);
    float*    p_h1   = (float*)sym(g_h1);
    float*    p_mid  = (float*)sym(g_mid);
    float*    p_h2   = (float*)sym(g_h2);
    float*    p_y    = (float*)sym(g_y);
    float*    out    = (float*)d_out;

    // --- GCN branch ---
    fill_f<<<(NN + 255) / 256, 256>>>(p_deg, 0.f, NN);
    fill_u<<<(GG * MM * 32 + 255) / 256, 256>>>(p_adj, 0u, GG * MM * 32);
    deg_kernel<<<(E + 255) / 256, 256>>>(ei, E, p_deg);
    dinv_kernel<<<NN / 256, 256>>>(p_deg, p_dinv);
    gemm_k<0, 0><<<dim3(NN / 64, HH / 64), 256>>>(x, gcn_w, nullptr, nullptr, p_xw, HH, HH);
    xlocal_init<<<NN * HH / 256, 256>>>(p_xw, p_dinv, gcn_b, p_xl);
    edge_scatter<<<(E * 64 + 255) / 256, 256>>>(ei, E, p_xw, p_dinv, p_xl);

    // --- SPD distances ---
    adj_kernel<<<(E + 255) / 256, 256>>>(ei, E, p_adj);
    cudaFuncSetAttribute(spd_kernel, cudaFuncAttributeMaxDynamicSharedMemorySize, MM * 33 * 4);
    spd_kernel<<<64, 128, MM * 33 * 4>>>(p_adj, p_dist);

    // --- Graphormer layer ---
    gemm_k<0, 0><<<dim3(NN / 64, QKVD / 64), 256>>>(x, qkv_w, qkv_b, nullptr, p_qkv, HH, QKVD);
    attn_kernel<<<dim3(GG * NHEADS, MM / 128), 128>>>(p_qkv, p_dist, bias_e, p_attn);
    gemm_k<0, 1><<<dim3(NN / 64, HH / 64), 256>>>(p_attn, proj_w, proj_b, x, p_tmp, HH, HH);
    ln_kernel<<<NN, 256>>>(p_tmp, nullptr, nullptr, ln1_g, ln1_b, p_h1);
    gemm_k<1, 0><<<dim3(NN / 64, FFND / 64), 256>>>(p_h1, ffn1_w, ffn1_b, nullptr, p_mid, HH, FFND);
    gemm_k<0, 1><<<dim3(NN / 64, HH / 64), 256>>>(p_mid, ffn2_w, ffn2_b, p_h1, p_tmp, FFND, HH);
    ln_kernel<<<NN, 256>>>(p_tmp, nullptr, nullptr, ln2_g, ln2_b, p_h2);

    // --- GPS combine + outer FFN ---
    ln_kernel<<<NN, 256>>>(x, p_xl, p_h2, oln1_g, oln1_b, p_y);
    gemm_k<1, 0><<<dim3(NN / 64, FFND / 64), 256>>>(p_y, offn1_w, offn1_b, nullptr, p_mid, HH, FFND);
    gemm_k<0, 1><<<dim3(NN / 64, HH / 64), 256>>>(p_mid, offn2_w, offn2_b, p_y, p_tmp, FFND, HH);
    ln_kernel<<<NN, 256>>>(p_tmp, nullptr, nullptr, oln2_g, oln2_b, out);
}

// round 2
// speedup vs baseline: 1.5672x; 1.5672x over previous
#include <cuda_runtime.h>
#include <cuda_bf16.h>
#include <cstdint>
#include <math.h>

// Problem constants (fixed by the dataset)
#define GG 8
#define MM 1024
#define NN 8192          // GG*MM
#define HH 256
#define NHEADS 8
#define HDIM 32
#define FFND 1024
#define QKVD 768

// ---------------- scratch (device globals; no allocation) ----------------
__device__ float    g_deg [NN];
__device__ float    g_dinv[NN];
__device__ float    g_xw  [NN * HH];
__device__ float    g_xl  [NN * HH];
__device__ uint32_t g_adj [GG * MM * 32];
__device__ unsigned char g_dist[(size_t)GG * MM * MM];   // 8 MB
__device__ float    g_qkv [(size_t)NN * QKVD];
__device__ float    g_tmp [NN * HH];
__device__ float    g_h1  [NN * HH];
__device__ float    g_h2  [NN * HH];
__device__ float    g_y   [NN * HH];

#define AL16 __align__(16)
__device__ AL16 __nv_bfloat16 g_x_hi[NN * HH],  g_x_lo[NN * HH];
__device__ AL16 __nv_bfloat16 g_at_hi[NN * HH], g_at_lo[NN * HH];
__device__ AL16 __nv_bfloat16 g_h1_hi[NN * HH], g_h1_lo[NN * HH];
__device__ AL16 __nv_bfloat16 g_y_hi[NN * HH],  g_y_lo[NN * HH];
__device__ AL16 __nv_bfloat16 g_mid_hi[(size_t)NN * FFND], g_mid_lo[(size_t)NN * FFND];
// all weights split into one pool (offsets below)
__device__ AL16 __nv_bfloat16 g_whi[1376256], g_wlo[1376256];
// offsets: gcn 0, qkv 65536, proj 262144, ffn1 327680, ffn2 589824, offn1 851968, offn2 1114112
#define OFF_GCN   0
#define OFF_QKV   65536
#define OFF_PROJ  262144
#define OFF_FFN1  327680
#define OFF_FFN2  589824
#define OFF_OFFN1 851968
#define OFF_OFFN2 1114112

// ---------------- utility fills / splits ----------------
__global__ void fill_f(float* p, float v, int n) {
    int i = blockIdx.x * blockDim.x + threadIdx.x;
    if (i < n) p[i] = v;
}
__global__ void fill_u(uint32_t* p, uint32_t v, int n) {
    int i = blockIdx.x * blockDim.x + threadIdx.x;
    if (i < n) p[i] = v;
}
__global__ void split_k(const float* __restrict__ in, __nv_bfloat16* __restrict__ hi,
                        __nv_bfloat16* __restrict__ lo, int n) {
    int i = blockIdx.x * blockDim.x + threadIdx.x;
    if (i >= n) return;
    float v = in[i];
    __nv_bfloat16 h = __float2bfloat16(v);
    hi[i] = h;
    lo[i] = __float2bfloat16(v - __bfloat162float(h));
}

// ---------------- GCN pieces ----------------
__global__ void deg_kernel(const int* __restrict__ ei, int E, float* __restrict__ deg) {
    int e = blockIdx.x * blockDim.x + threadIdx.x;
    if (e < E) atomicAdd(&deg[ei[E + e]], 1.0f);
}
__global__ void dinv_kernel(const float* __restrict__ deg, float* __restrict__ dinv) {
    int i = blockIdx.x * blockDim.x + threadIdx.x;
    if (i < NN) dinv[i] = rsqrtf(deg[i] + 1.0f);
}
__global__ void xlocal_init(const float* __restrict__ xw, const float* __restrict__ dinv,
                            const float* __restrict__ gcn_b, float* __restrict__ xl) {
    int idx = blockIdx.x * blockDim.x + threadIdx.x;
    int i = idx >> 8, c = idx & 255;
    float di = dinv[i];
    xl[idx] = xw[idx] * di * di + gcn_b[c];
}
__global__ void edge_scatter(const int* __restrict__ ei, int E,
                             const float* __restrict__ xw, const float* __restrict__ dinv,
                             float* __restrict__ xl) {
    int idx = blockIdx.x * blockDim.x + threadIdx.x;
    int e  = idx >> 6;
    int c4 = (idx & 63) * 4;
    if (e >= E) return;
    int s = __ldg(&ei[e]);
    int d = __ldg(&ei[E + e]);
    float w = __ldg(&dinv[s]) * __ldg(&dinv[d]);
    const float4 v = *(const float4*)&xw[(size_t)s * HH + c4];
    float* dst = &xl[(size_t)d * HH + c4];
    atomicAdd(dst + 0, v.x * w);
    atomicAdd(dst + 1, v.y * w);
    atomicAdd(dst + 2, v.z * w);
    atomicAdd(dst + 3, v.w * w);
}

// ---------------- SPD: adjacency bitsets + bitset BFS ----------------
__global__ void adj_kernel(const int* __restrict__ ei, int E, uint32_t* __restrict__ adj) {
    int e = blockIdx.x * blockDim.x + threadIdx.x;
    if (e >= E) return;
    int s = ei[e], d = ei[E + e];
    if (s == d || (s >> 10) != (d >> 10)) return;
    int g = s >> 10, ls = s & 1023, ld = d & 1023;
    atomicOr(&adj[((size_t)g * MM + ls) * 32 + (ld >> 5)], 1u << (ld & 31));
    atomicOr(&adj[((size_t)g * MM + ld) * 32 + (ls >> 5)], 1u << (ls & 31));
}

__launch_bounds__(128)
__global__ void spd_kernel(const uint32_t* __restrict__ adj, unsigned char* __restrict__ dist) {
    extern __shared__ uint32_t adj_sh[];   // [1024][33] padded
    int g = blockIdx.x >> 3;
    const uint32_t* ga = adj + (size_t)g * MM * 32;
    for (int idx = threadIdx.x; idx < MM * 32; idx += blockDim.x) {
        int r = idx >> 5, w = idx & 31;
        adj_sh[r * 33 + w] = ga[idx];
    }
    __syncthreads();

    int i = (blockIdx.x & 7) * 128 + threadIdx.x;
    unsigned char* drow = dist + ((size_t)g * MM + i) * MM;

    uint32_t reach[32], frontier[32];
#pragma unroll
    for (int w = 0; w < 32; ++w) {
        uint32_t a = adj_sh[i * 33 + w];
        reach[w] = a; frontier[w] = a;
    }
#pragma unroll
    for (int w = 0; w < 32; ++w) {
        uint32_t f = frontier[w];
        uint32_t* dp = (uint32_t*)(drow + w * 32);
#pragma unroll
        for (int q = 0; q < 8; ++q) {
            uint32_t nib = (f >> (q * 4)) & 0xF;
            uint32_t word = 0x06060606u;
            if (nib & 1) word = (word & 0xFFFFFF00u) | 0x01u;
            if (nib & 2) word = (word & 0xFFFF00FFu) | 0x0100u;
            if (nib & 4) word = (word & 0xFF00FFFFu) | 0x010000u;
            if (nib & 8) word = (word & 0x00FFFFFFu) | 0x01000000u;
            dp[q] = word;
        }
    }
    drow[i] = 0;
    reach[i >> 5] |= 1u << (i & 31);

    for (int d = 2; d <= 5; ++d) {
        uint32_t nw[32];
#pragma unroll
        for (int w = 0; w < 32; ++w) nw[w] = 0u;
        for (int w = 0; w < 32; ++w) {
            uint32_t f = frontier[w];
            while (f) {
                int b = __ffs((int)f) - 1;
                f &= f - 1;
                const uint32_t* aj = &adj_sh[(w * 32 + b) * 33];
#pragma unroll
                for (int ww = 0; ww < 32; ++ww) nw[ww] |= aj[ww];
            }
        }
        uint32_t any = 0;
        uint32_t rep = (uint32_t)d * 0x01010101u;
#pragma unroll
        for (int w = 0; w < 32; ++w) {
            uint32_t newly = nw[w] & ~reach[w];
            frontier[w] = newly;
            reach[w] |= newly;
            any |= newly;
            if (newly) {
                uint32_t* dp = (uint32_t*)(drow + w * 32);
#pragma unroll
                for (int q = 0; q < 8; ++q) {
                    uint32_t nib = (newly >> (q * 4)) & 0xF;
                    if (nib) {
                        uint32_t m = ((nib & 1) ? 0xFFu : 0u) | ((nib & 2) ? 0xFF00u : 0u)
                                   | ((nib & 4) ? 0xFF0000u : 0u) | ((nib & 8) ? 0xFF000000u : 0u);
                        dp[q] = (dp[q] & ~m) | (rep & m);
                    }
                }
            }
        }
        if (!any) break;
    }
}

// ---------------- bf16x3 tensor-core GEMM: C = A @ W^T (+bias)(+gelu)(+res) ----------------
// A:[rows,K], W:[F,K] both split into hi/lo bf16. Block tile 128x128x32, 8 warps (64x32 each).
#define CP16(dst, src) asm volatile("cp.async.cg.shared.global [%0], [%1], 16;\n" :: "r"(dst), "l"(src))
#define MMA16816(d, a0, a1, a2, a3, b0, b1) \
    asm volatile("mma.sync.aligned.m16n8k16.row.col.f32.bf16.bf16.f32 " \
                 "{%0,%1,%2,%3}, {%4,%5,%6,%7}, {%8,%9}, {%0,%1,%2,%3};" \
                 : "+f"(d[0]), "+f"(d[1]), "+f"(d[2]), "+f"(d[3]) \
                 : "r"(a0), "r"(a1), "r"(a2), "r"(a3), "r"(b0), "r"(b1))

template <int GELU, int RES, int OUTBF16>
__launch_bounds__(256)
__global__ void gemm_bf16(const __nv_bfloat16* __restrict__ Ahi, const __nv_bfloat16* __restrict__ Alo,
                          const __nv_bfloat16* __restrict__ Whi, const __nv_bfloat16* __restrict__ Wlo,
                          const float* __restrict__ bias, const float* __restrict__ res,
                          float* __restrict__ C, __nv_bfloat16* __restrict__ Chi,
                          __nv_bfloat16* __restrict__ Clo, int K, int F) {
    extern __shared__ unsigned char smp[];
    const int STG = 40960;                 // bytes per stage: 4 arrays x 128 rows x 80B
    int m0 = blockIdx.x * 128, f0 = blockIdx.y * 128;
    int tid = threadIdx.x, lane = tid & 31, warp = tid >> 5;
    int g = lane >> 2, tg = lane & 3;
    int wm = (warp >> 2) * 64, wn = (warp & 3) * 32;
    uint32_t smem_base = (uint32_t)__cvta_generic_to_shared(smp);

    float acc[4][4][4];
#pragma unroll
    for (int a = 0; a < 4; ++a)
#pragma unroll
        for (int b = 0; b < 4; ++b)
#pragma unroll
            for (int c = 0; c < 4; ++c) acc[a][b][c] = 0.f;

    auto load_stage = [&](int s, int k0) {
        uint32_t db = smem_base + s * STG;
        const __nv_bfloat16* srcs[4] = {
            Ahi + (size_t)m0 * K + k0, Alo + (size_t)m0 * K + k0,
            Whi + (size_t)f0 * K + k0, Wlo + (size_t)f0 * K + k0 };
#pragma unroll
        for (int arr = 0; arr < 4; ++arr) {
            const __nv_bfloat16* bp = srcs[arr];
            uint32_t ab = db + arr * 10240;
#pragma unroll
            for (int c = 0; c < 2; ++c) {
                int t = tid + c * 256;
                int row = t >> 2, ch = t & 3;
                CP16(ab + row * 80 + ch * 16, bp + (size_t)row * K + ch * 8);
            }
        }
        asm volatile("cp.async.commit_group;\n" ::);
    };

    int nk = K >> 5;
    load_stage(0, 0);
    for (int kc = 0; kc < nk; ++kc) {
        if (kc + 1 < nk) {
            load_stage((kc + 1) & 1, (kc + 1) << 5);
            asm volatile("cp.async.wait_group 1;\n" ::);
        } else {
            asm volatile("cp.async.wait_group 0;\n" ::);
        }
        __syncthreads();

        const uint32_t* Ah = (const uint32_t*)(smp + (kc & 1) * STG);
        const uint32_t* Al = Ah + 2560;
        const uint32_t* Wh = Ah + 5120;
        const uint32_t* Wl = Ah + 7680;
#pragma unroll
        for (int ks = 0; ks < 2; ++ks) {
            int ku = ks * 8;
            uint32_t bh[4][2], bl[4][2];
#pragma unroll
            for (int nt = 0; nt < 4; ++nt) {
                int idx = (wn + nt * 8 + g) * 20 + ku + tg;
                bh[nt][0] = Wh[idx]; bh[nt][1] = Wh[idx + 4];
                bl[nt][0] = Wl[idx]; bl[nt][1] = Wl[idx + 4];
            }
#pragma unroll
            for (int mt = 0; mt < 4; ++mt) {
                int i0 = (wm + mt * 16 + g) * 20 + ku + tg;
                int i1 = i0 + 160;
                uint32_t ah0 = Ah[i0], ah1 = Ah[i1], ah2 = Ah[i0 + 4], ah3 = Ah[i1 + 4];
                uint32_t al0 = Al[i0], al1 = Al[i1], al2 = Al[i0 + 4], al3 = Al[i1 + 4];
#pragma unroll
                for (int nt = 0; nt < 4; ++nt) {
                    MMA16816(acc[mt][nt], ah0, ah1, ah2, ah3, bh[nt][0], bh[nt][1]);
                    MMA16816(acc[mt][nt], ah0, ah1, ah2, ah3, bl[nt][0], bl[nt][1]);
                    MMA16816(acc[mt][nt], al0, al1, al2, al3, bh[nt][0], bh[nt][1]);
                }
            }
        }
        __syncthreads();
    }

    // epilogue
#pragma unroll
    for (int mt = 0; mt < 4; ++mt) {
#pragma unroll
        for (int half = 0; half < 2; ++half) {
            int row = m0 + wm + mt * 16 + g + half * 8;
#pragma unroll
            for (int nt = 0; nt < 4; ++nt) {
                int col = f0 + wn + nt * 8 + tg * 2;
                float v0 = acc[mt][nt][half * 2 + 0];
                float v1 = acc[mt][nt][half * 2 + 1];
                if (bias) { v0 += bias[col]; v1 += bias[col + 1]; }
                if (GELU) { v0 = v0 * normcdff(v0); v1 = v1 * normcdff(v1); }
                if (RES)  { v0 += res[(size_t)row * F + col]; v1 += res[(size_t)row * F + col + 1]; }
                if (OUTBF16) {
                    __nv_bfloat16 h0 = __float2bfloat16(v0), h1 = __float2bfloat16(v1);
                    __nv_bfloat16 l0 = __float2bfloat16(v0 - __bfloat162float(h0));
                    __nv_bfloat16 l1 = __float2bfloat16(v1 - __bfloat162float(h1));
                    *(__nv_bfloat162*)(Chi + (size_t)row * F + col) = __nv_bfloat162(h0, h1);
                    *(__nv_bfloat162*)(Clo + (size_t)row * F + col) = __nv_bfloat162(l0, l1);
                } else {
                    float2 o; o.x = v0; o.y = v1;
                    *(float2*)(C + (size_t)row * F + col) = o;
                }
            }
        }
    }
}

// ---------------- fused attention (online softmax), 1 thread = 1 query row ----------------
__launch_bounds__(128)
__global__ void attn_kernel(const float* __restrict__ qkv, const unsigned char* __restrict__ dist,
                            const float* __restrict__ bias_emb,
                            __nv_bfloat16* __restrict__ ohi, __nv_bfloat16* __restrict__ olo) {
    __shared__ float Ks[128][36];
    __shared__ float Vs[128][36];
    __shared__ float btab[8];
    int gh = blockIdx.x;
    int g = gh >> 3, h = gh & 7;
    int i = blockIdx.y * 128 + threadIdx.x;
    if (threadIdx.x < 7) btab[threadIdx.x] = bias_emb[threadIdx.x];

    const float* qp = qkv + ((size_t)(g * MM + i)) * QKVD + h * HDIM;
    float q[32];
#pragma unroll
    for (int d = 0; d < 32; d += 4) {
        float4 t = *(const float4*)(qp + d);
        q[d] = t.x; q[d + 1] = t.y; q[d + 2] = t.z; q[d + 3] = t.w;
    }
    float acc[32];
#pragma unroll
    for (int d = 0; d < 32; ++d) acc[d] = 0.f;
    float mx = -1e30f, l = 0.f;
    const unsigned char* drow = dist + ((size_t)(g * MM + i)) * MM;
    const float scale = 0.17677669529663687f;

    for (int j0 = 0; j0 < MM; j0 += 128) {
        const float* kp = qkv + ((size_t)(g * MM + j0 + threadIdx.x)) * QKVD + HH + h * HDIM;
        const float* vp = kp + HH;
#pragma unroll
        for (int d = 0; d < 32; d += 4) {
            *(float4*)&Ks[threadIdx.x][d] = *(const float4*)(kp + d);
            *(float4*)&Vs[threadIdx.x][d] = *(const float4*)(vp + d);
        }
        __syncthreads();

        for (int jj = 0; jj < 128; jj += 4) {
            uint32_t d4 = *(const uint32_t*)(drow + j0 + jj);
#pragma unroll
            for (int t = 0; t < 4; ++t) {
                int j = jj + t;
                float s0 = 0.f, s1 = 0.f, s2 = 0.f, s3 = 0.f;
#pragma unroll
                for (int d = 0; d < 32; d += 16) {
                    float4 k0 = *(const float4*)&Ks[j][d + 0];
                    float4 k1 = *(const float4*)&Ks[j][d + 4];
                    float4 k2 = *(const float4*)&Ks[j][d + 8];
                    float4 k3 = *(const float4*)&Ks[j][d + 12];
                    s0 = fmaf(q[d+0], k0.x, fmaf(q[d+1], k0.y, fmaf(q[d+2], k0.z, fmaf(q[d+3], k0.w, s0))));
                    s1 = fmaf(q[d+4], k1.x, fmaf(q[d+5], k1.y, fmaf(q[d+6], k1.z, fmaf(q[d+7], k1.w, s1))));
                    s2 = fmaf(q[d+8], k2.x, fmaf(q[d+9], k2.y, fmaf(q[d+10],k2.z, fmaf(q[d+11],k2.w, s2))));
                    s3 = fmaf(q[d+12],k3.x, fmaf(q[d+13],k3.y, fmaf(q[d+14],k3.z, fmaf(q[d+15],k3.w, s3))));
                }
                float s = (s0 + s1) + (s2 + s3);
                s = s * scale + btab[(d4 >> (8 * t)) & 0xFF];
                if (s > mx) {
                    float corr = __expf(mx - s);
                    mx = s;
                    l *= corr;
#pragma unroll
                    for (int d = 0; d < 32; ++d) acc[d] *= corr;
                }
                float p = __expf(s - mx);
                l += p;
#pragma unroll
                for (int d = 0; d < 32; d += 4) {
                    float4 v4 = *(const float4*)&Vs[j][d];
                    acc[d + 0] = fmaf(p, v4.x, acc[d + 0]);
                    acc[d + 1] = fmaf(p, v4.y, acc[d + 1]);
                    acc[d + 2] = fmaf(p, v4.z, acc[d + 2]);
                    acc[d + 3] = fmaf(p, v4.w, acc[d + 3]);
                }
            }
        }
        __syncthreads();
    }
    float inv = 1.f / l;
    size_t ob = ((size_t)(g * MM + i)) * HH + h * HDIM;
#pragma unroll
    for (int d = 0; d < 32; d += 2) {
        float o0 = acc[d] * inv, o1 = acc[d + 1] * inv;
        __nv_bfloat16 h0 = __float2bfloat16(o0), h1 = __float2bfloat16(o1);
        __nv_bfloat16 l0 = __float2bfloat16(o0 - __bfloat162float(h0));
        __nv_bfloat16 l1 = __float2bfloat16(o1 - __bfloat162float(h1));
        *(__nv_bfloat162*)(ohi + ob + d) = __nv_bfloat162(h0, h1);
        *(__nv_bfloat162*)(olo + ob + d) = __nv_bfloat162(l0, l1);
    }
}

// ---------------- LayerNorm (up to 3 summed inputs), one block per row ----------------
__launch_bounds__(256)
__global__ void ln_kernel(const float* __restrict__ a, const float* __restrict__ b,
                          const float* __restrict__ c, const float* __restrict__ gam,
                          const float* __restrict__ bet, float* __restrict__ out,
                          __nv_bfloat16* __restrict__ ohi, __nv_bfloat16* __restrict__ olo) {
    int row = blockIdx.x, t = threadIdx.x;
    size_t idx = (size_t)row * HH + t;
    float v = a[idx];
    if (b) v += b[idx];
    if (c) v += c[idx];
    float s = v, s2 = v * v;
#pragma unroll
    for (int o = 16; o; o >>= 1) {
        s  += __shfl_xor_sync(0xFFFFFFFFu, s, o);
        s2 += __shfl_xor_sync(0xFFFFFFFFu, s2, o);
    }
    __shared__ float sh1[8], sh2[8];
    int w = t >> 5, ln = t & 31;
    if (ln == 0) { sh1[w] = s; sh2[w] = s2; }
    __syncthreads();
    if (w == 0) {
        s  = (ln < 8) ? sh1[ln] : 0.f;
        s2 = (ln < 8) ? sh2[ln] : 0.f;
#pragma unroll
        for (int o = 4; o; o >>= 1) {
            s  += __shfl_xor_sync(0xFFFFFFFFu, s, o);
            s2 += __shfl_xor_sync(0xFFFFFFFFu, s2, o);
        }
        if (ln == 0) { sh1[0] = s; sh2[0] = s2; }
    }
    __syncthreads();
    float mean = sh1[0] * (1.f / HH);
    float var  = sh2[0] * (1.f / HH) - mean * mean;
    float r = (v - mean) * rsqrtf(var + 1e-5f) * gam[t] + bet[t];
    out[idx] = r;
    if (ohi) {
        __nv_bfloat16 hh = __float2bfloat16(r);
        ohi[idx] = hh;
        olo[idx] = __float2bfloat16(r - __bfloat162float(hh));
    }
}

// ---------------- host ----------------
static void* sym(const void* s) { void* p = nullptr; cudaGetSymbolAddress(&p, s); return p; }

extern "C" void kernel_launch(void* const* d_in, const int* in_sizes, int n_in,
                              void* d_out, int out_size) {
    const float* x      = (const float*)d_in[0];
    const float* gcn_w  = (const float*)d_in[1];
    const float* gcn_b  = (const float*)d_in[2];
    const float* qkv_w  = (const float*)d_in[3];
    const float* qkv_b  = (const float*)d_in[4];
    const float* proj_w = (const float*)d_in[5];
    const float* proj_b = (const float*)d_in[6];
    const float* ln1_g  = (const float*)d_in[7];
    const float* ln1_b  = (const float*)d_in[8];
    const float* ln2_g  = (const float*)d_in[9];
    const float* ln2_b  = (const float*)d_in[10];
    const float* ffn1_w = (const float*)d_in[11];
    const float* ffn1_b = (const float*)d_in[12];
    const float* ffn2_w = (const float*)d_in[13];
    const float* ffn2_b = (const float*)d_in[14];
    const float* bias_e = (const float*)d_in[15];
    const float* oln1_g = (const float*)d_in[16];
    const float* oln1_b = (const float*)d_in[17];
    const float* oln2_g = (const float*)d_in[18];
    const float* oln2_b = (const float*)d_in[19];
    const float* offn1_w= (const float*)d_in[20];
    const float* offn1_b= (const float*)d_in[21];
    const float* offn2_w= (const float*)d_in[22];
    const float* offn2_b= (const float*)d_in[23];
    const int*   ei     = (const int*)d_in[24];
    int E = in_sizes[24] / 2;

    float*    p_deg  = (float*)sym(g_deg);
    float*    p_dinv = (float*)sym(g_dinv);
    float*    p_xw   = (float*)sym(g_xw);
    float*    p_xl   = (float*)sym(g_xl);
    uint32_t* p_adj  = (uint32_t*)sym(g_adj);
    unsigned char* p_dist = (unsigned char*)sym(g_dist);
    float*    p_qkv  = (float*)sym(g_qkv);
    float*    p_tmp  = (float*)sym(g_tmp);
    float*    p_h1   = (float*)sym(g_h1);
    float*    p_h2   = (float*)sym(g_h2);
    float*    p_y    = (float*)sym(g_y);
    __nv_bfloat16* x_hi  = (__nv_bfloat16*)sym(g_x_hi);
    __nv_bfloat16* x_lo  = (__nv_bfloat16*)sym(g_x_lo);
    __nv_bfloat16* at_hi = (__nv_bfloat16*)sym(g_at_hi);
    __nv_bfloat16* at_lo = (__nv_bfloat16*)sym(g_at_lo);
    __nv_bfloat16* h1_hi = (__nv_bfloat16*)sym(g_h1_hi);
    __nv_bfloat16* h1_lo = (__nv_bfloat16*)sym(g_h1_lo);
    __nv_bfloat16* y_hi  = (__nv_bfloat16*)sym(g_y_hi);
    __nv_bfloat16* y_lo  = (__nv_bfloat16*)sym(g_y_lo);
    __nv_bfloat16* mid_hi= (__nv_bfloat16*)sym(g_mid_hi);
    __nv_bfloat16* mid_lo= (__nv_bfloat16*)sym(g_mid_lo);
    __nv_bfloat16* whi   = (__nv_bfloat16*)sym(g_whi);
    __nv_bfloat16* wlo   = (__nv_bfloat16*)sym(g_wlo);
    float* out = (float*)d_out;

    const int SMEM = 81920;
    cudaFuncSetAttribute(gemm_bf16<0,0,0>, cudaFuncAttributeMaxDynamicSharedMemorySize, SMEM);
    cudaFuncSetAttribute(gemm_bf16<0,1,0>, cudaFuncAttributeMaxDynamicSharedMemorySize, SMEM);
    cudaFuncSetAttribute(gemm_bf16<1,0,1>, cudaFuncAttributeMaxDynamicSharedMemorySize, SMEM);
    cudaFuncSetAttribute(spd_kernel, cudaFuncAttributeMaxDynamicSharedMemorySize, MM * 33 * 4);

    // --- splits (x + all weights) ---
    split_k<<<(NN * HH + 255) / 256, 256>>>(x, x_hi, x_lo, NN * HH);
    split_k<<<(65536 + 255) / 256, 256>>>(gcn_w,  whi + OFF_GCN,  wlo + OFF_GCN,  65536);
    split_k<<<(196608 + 255) / 256, 256>>>(qkv_w, whi + OFF_QKV,  wlo + OFF_QKV,  196608);
    split_k<<<(65536 + 255) / 256, 256>>>(proj_w, whi + OFF_PROJ, wlo + OFF_PROJ, 65536);
    split_k<<<(262144 + 255) / 256, 256>>>(ffn1_w, whi + OFF_FFN1, wlo + OFF_FFN1, 262144);
    split_k<<<(262144 + 255) / 256, 256>>>(ffn2_w, whi + OFF_FFN2, wlo + OFF_FFN2, 262144);
    split_k<<<(262144 + 255) / 256, 256>>>(offn1_w, whi + OFF_OFFN1, wlo + OFF_OFFN1, 262144);
    split_k<<<(262144 + 255) / 256, 256>>>(offn2_w, whi + OFF_OFFN2, wlo + OFF_OFFN2, 262144);

    // --- GCN branch ---
    fill_f<<<(NN + 255) / 256, 256>>>(p_deg, 0.f, NN);
    fill_u<<<(GG * MM * 32 + 255) / 256, 256>>>(p_adj, 0u, GG * MM * 32);
    deg_kernel<<<(E + 255) / 256, 256>>>(ei, E, p_deg);
    dinv_kernel<<<NN / 256, 256>>>(p_deg, p_dinv);
    gemm_bf16<0,0,0><<<dim3(NN/128, HH/128), 256, SMEM>>>(x_hi, x_lo, whi + OFF_GCN, wlo + OFF_GCN,
        nullptr, nullptr, p_xw, nullptr, nullptr, HH, HH);
    xlocal_init<<<NN * HH / 256, 256>>>(p_xw, p_dinv, gcn_b, p_xl);
    edge_scatter<<<(E * 64 + 255) / 256, 256>>>(ei, E, p_xw, p_dinv, p_xl);

    // --- SPD distances ---
    adj_kernel<<<(E + 255) / 256, 256>>>(ei, E, p_adj);
    spd_kernel<<<64, 128, MM * 33 * 4>>>(p_adj, p_dist);

    // --- Graphormer layer ---
    gemm_bf16<0,0,0><<<dim3(NN/128, QKVD/128), 256, SMEM>>>(x_hi, x_lo, whi + OFF_QKV, wlo + OFF_QKV,
        qkv_b, nullptr, p_qkv, nullptr, nullptr, HH, QKVD);
    attn_kernel<<<dim3(GG * NHEADS, MM / 128), 128>>>(p_qkv, p_dist, bias_e, at_hi, at_lo);
    gemm_bf16<0,1,0><<<dim3(NN/128, HH/128), 256, SMEM>>>(at_hi, at_lo, whi + OFF_PROJ, wlo + OFF_PROJ,
        proj_b, x, p_tmp, nullptr, nullptr, HH, HH);
    ln_kernel<<<NN, 256>>>(p_tmp, nullptr, nullptr, ln1_g, ln1_b, p_h1, h1_hi, h1_lo);
    gemm_bf16<1,0,1><<<dim3(NN/128, FFND/128), 256, SMEM>>>(h1_hi, h1_lo, whi + OFF_FFN1, wlo + OFF_FFN1,
        ffn1_b, nullptr, nullptr, mid_hi, mid_lo, HH, FFND);
    gemm_bf16<0,1,0><<<dim3(NN/128, HH/128), 256, SMEM>>>(mid_hi, mid_lo, whi + OFF_FFN2, wlo + OFF_FFN2,
        ffn2_b, p_h1, p_tmp, nullptr, nullptr, FFND, HH);
    ln_kernel<<<NN, 256>>>(p_tmp, nullptr, nullptr, ln2_g, ln2_b, p_h2, nullptr, nullptr);

    // --- GPS combine + outer FFN ---
    ln_kernel<<<NN, 256>>>(x, p_xl, p_h2, oln1_g, oln1_b, p_y, y_hi, y_lo);
    gemm_bf16<1,0,1><<<dim3(NN/128, FFND/128), 256, SMEM>>>(y_hi, y_lo, whi + OFF_OFFN1, wlo + OFF_OFFN1,
        offn1_b, nullptr, nullptr, mid_hi, mid_lo, HH, FFND);
    gemm_bf16<0,1,0><<<dim3(NN/128, HH/128), 256, SMEM>>>(mid_hi, mid_lo, whi + OFF_OFFN2, wlo + OFF_OFFN2,
        offn2_b, p_y, p_tmp, nullptr, nullptr, FFND, HH);
    ln_kernel<<<NN, 256>>>(p_tmp, nullptr, nullptr, oln2_g, oln2_b, out, nullptr, nullptr);
}

// round 3
// speedup vs baseline: 1.9831x; 1.2654x over previous
#include <cuda_runtime.h>
#include <cuda_bf16.h>
#include <cstdint>
#include <math.h>

// Problem constants (fixed by the dataset)
#define GG 8
#define MM 1024
#define NN 8192          // GG*MM
#define HH 256
#define NHEADS 8
#define HDIM 32
#define FFND 1024
#define QKVD 768

// ---------------- scratch (device globals; no allocation) ----------------
__device__ float    g_deg [NN];
__device__ float    g_dinv[NN];
__device__ float    g_xw  [NN * HH];
__device__ float    g_xl  [NN * HH];
__device__ uint32_t g_adj [GG * MM * 32];
__device__ unsigned char g_dist[(size_t)GG * MM * MM];   // 8 MB
__device__ float    g_qkv [(size_t)NN * QKVD];
__device__ float    g_tmp [NN * HH];
__device__ float    g_h1  [NN * HH];
__device__ float    g_h2  [NN * HH];
__device__ float    g_y   [NN * HH];

#define AL16 __align__(16)
__device__ AL16 __nv_bfloat16 g_x_hi[NN * HH],  g_x_lo[NN * HH];
__device__ AL16 __nv_bfloat16 g_at_hi[NN * HH], g_at_lo[NN * HH];
__device__ AL16 __nv_bfloat16 g_h1_hi[NN * HH], g_h1_lo[NN * HH];
__device__ AL16 __nv_bfloat16 g_y_hi[NN * HH],  g_y_lo[NN * HH];
__device__ AL16 __nv_bfloat16 g_mid_hi[(size_t)NN * FFND], g_mid_lo[(size_t)NN * FFND];
// attention operand layouts
__device__ AL16 __nv_bfloat16 g_q_hi[NN * HH],  g_q_lo[NN * HH];
__device__ AL16 __nv_bfloat16 g_k_hi[NN * HH],  g_k_lo[NN * HH];
__device__ AL16 __nv_bfloat16 g_vt_hi[GG * NHEADS * HDIM * MM], g_vt_lo[GG * NHEADS * HDIM * MM];
// all weights split into one pool (offsets below)
__device__ AL16 __nv_bfloat16 g_whi[1376256], g_wlo[1376256];
#define OFF_GCN   0
#define OFF_QKV   65536
#define OFF_PROJ  262144
#define OFF_FFN1  327680
#define OFF_FFN2  589824
#define OFF_OFFN1 851968
#define OFF_OFFN2 1114112

// ---------------- helpers ----------------
__device__ __forceinline__ uint32_t packbf(float lo, float hi) {
    uint32_t r;
    asm("cvt.rn.bf16x2.f32 %0, %1, %2;" : "=r"(r) : "f"(hi), "f"(lo));
    return r;
}
__device__ __forceinline__ float ex2f(float x) {
    float y; asm("ex2.approx.f32 %0, %1;" : "=f"(y) : "f"(x)); return y;
}
__device__ __forceinline__ void split2(float a, float b, uint32_t& hi, uint32_t& lo) {
    uint32_t h = packbf(a, b);
    float ha = __uint_as_float(h << 16);
    float hb = __uint_as_float(h & 0xffff0000u);
    hi = h;
    lo = packbf(a - ha, b - hb);
}

// ---------------- fused splits ----------------
__global__ void split4(const float4* __restrict__ in, __nv_bfloat16* __restrict__ hi,
                       __nv_bfloat16* __restrict__ lo, int n4) {
    int i = blockIdx.x * blockDim.x + threadIdx.x;
    if (i >= n4) return;
    float4 v = in[i];
    uint32_t h0, l0, h1, l1;
    split2(v.x, v.y, h0, l0);
    split2(v.z, v.w, h1, l1);
    *(uint2*)(hi + i * 4) = make_uint2(h0, h1);
    *(uint2*)(lo + i * 4) = make_uint2(l0, l1);
}
// all 7 weights -> contiguous pool (same order), one kernel
__global__ void splitw(const float4* w0, const float4* w1, const float4* w2, const float4* w3,
                       const float4* w4, const float4* w5, const float4* w6,
                       __nv_bfloat16* __restrict__ hi, __nv_bfloat16* __restrict__ lo) {
    int i = blockIdx.x * blockDim.x + threadIdx.x;   // f4 index into pool
    if (i >= 344064) return;
    const float4* src; int base;
    if      (i < 16384)  { src = w0; base = 0; }
    else if (i < 65536)  { src = w1; base = 16384; }
    else if (i < 81920)  { src = w2; base = 65536; }
    else if (i < 147456) { src = w3; base = 81920; }
    else if (i < 212992) { src = w4; base = 147456; }
    else if (i < 278528) { src = w5; base = 212992; }
    else                 { src = w6; base = 278528; }
    float4 v = src[i - base];
    uint32_t h0, l0, h1, l1;
    split2(v.x, v.y, h0, l0);
    split2(v.z, v.w, h1, l1);
    *(uint2*)(hi + (size_t)i * 4) = make_uint2(h0, h1);
    *(uint2*)(lo + (size_t)i * 4) = make_uint2(l0, l1);
}

// ---------------- GCN / graph prep ----------------
__global__ void zero_prep(float* __restrict__ deg, uint32_t* __restrict__ adj) {
    int i = blockIdx.x * blockDim.x + threadIdx.x;
    if (i < GG * MM * 32) adj[i] = 0u;
    if (i < NN) deg[i] = 0.f;
}
__global__ void edge_prep(const int* __restrict__ ei, int E, float* __restrict__ deg,
                          uint32_t* __restrict__ adj) {
    int e = blockIdx.x * blockDim.x + threadIdx.x;
    if (e >= E) return;
    int s = ei[e], d = ei[E + e];
    atomicAdd(&deg[d], 1.0f);
    if (s == d || (s >> 10) != (d >> 10)) return;
    int g = s >> 10, ls = s & 1023, ld = d & 1023;
    atomicOr(&adj[((size_t)g * MM + ls) * 32 + (ld >> 5)], 1u << (ld & 31));
    atomicOr(&adj[((size_t)g * MM + ld) * 32 + (ls >> 5)], 1u << (ls & 31));
}
__global__ void dinv_kernel(const float* __restrict__ deg, float* __restrict__ dinv) {
    int i = blockIdx.x * blockDim.x + threadIdx.x;
    if (i < NN) dinv[i] = rsqrtf(deg[i] + 1.0f);
}
__global__ void xlocal_init(const float* __restrict__ xw, const float* __restrict__ dinv,
                            const float* __restrict__ gcn_b, float* __restrict__ xl) {
    int idx = blockIdx.x * blockDim.x + threadIdx.x;
    int i = idx >> 8, c = idx & 255;
    float di = dinv[i];
    xl[idx] = xw[idx] * di * di + gcn_b[c];
}
__global__ void edge_scatter(const int* __restrict__ ei, int E,
                             const float* __restrict__ xw, const float* __restrict__ dinv,
                             float* __restrict__ xl) {
    int idx = blockIdx.x * blockDim.x + threadIdx.x;
    int e  = idx >> 6;
    int c4 = (idx & 63) * 4;
    if (e >= E) return;
    int s = __ldg(&ei[e]);
    int d = __ldg(&ei[E + e]);
    float w = __ldg(&dinv[s]) * __ldg(&dinv[d]);
    const float4 v = *(const float4*)&xw[(size_t)s * HH + c4];
    float* dst = &xl[(size_t)d * HH + c4];
    atomicAdd(dst + 0, v.x * w);
    atomicAdd(dst + 1, v.y * w);
    atomicAdd(dst + 2, v.z * w);
    atomicAdd(dst + 3, v.w * w);
}

// ---------------- SPD bitset BFS ----------------
__launch_bounds__(128)
__global__ void spd_kernel(const uint32_t* __restrict__ adj, unsigned char* __restrict__ dist) {
    extern __shared__ uint32_t adj_sh[];   // [1024][33]
    int g = blockIdx.x >> 3;
    const uint32_t* ga = adj + (size_t)g * MM * 32;
    for (int idx = threadIdx.x; idx < MM * 32; idx += blockDim.x) {
        int r = idx >> 5, w = idx & 31;
        adj_sh[r * 33 + w] = ga[idx];
    }
    __syncthreads();

    int i = (blockIdx.x & 7) * 128 + threadIdx.x;
    unsigned char* drow = dist + ((size_t)g * MM + i) * MM;

    uint32_t reach[32], frontier[32];
#pragma unroll
    for (int w = 0; w < 32; ++w) {
        uint32_t a = adj_sh[i * 33 + w];
        reach[w] = a; frontier[w] = a;
    }
#pragma unroll
    for (int w = 0; w < 32; ++w) {
        uint32_t f = frontier[w];
        uint32_t* dp = (uint32_t*)(drow + w * 32);
#pragma unroll
        for (int q = 0; q < 8; ++q) {
            uint32_t nib = (f >> (q * 4)) & 0xF;
            uint32_t word = 0x06060606u;
            if (nib & 1) word = (word & 0xFFFFFF00u) | 0x01u;
            if (nib & 2) word = (word & 0xFFFF00FFu) | 0x0100u;
            if (nib & 4) word = (word & 0xFF00FFFFu) | 0x010000u;
            if (nib & 8) word = (word & 0x00FFFFFFu) | 0x01000000u;
            dp[q] = word;
        }
    }
    drow[i] = 0;
    reach[i >> 5] |= 1u << (i & 31);

    for (int d = 2; d <= 5; ++d) {
        uint32_t nw[32];
#pragma unroll
        for (int w = 0; w < 32; ++w) nw[w] = 0u;
        for (int w = 0; w < 32; ++w) {
            uint32_t f = frontier[w];
            while (f) {
                int b = __ffs((int)f) - 1;
                f &= f - 1;
                const uint32_t* aj = &adj_sh[(w * 32 + b) * 33];
#pragma unroll
                for (int ww = 0; ww < 32; ++ww) nw[ww] |= aj[ww];
            }
        }
        uint32_t any = 0;
        uint32_t rep = (uint32_t)d * 0x01010101u;
#pragma unroll
        for (int w = 0; w < 32; ++w) {
            uint32_t newly = nw[w] & ~reach[w];
            frontier[w] = newly;
            reach[w] |= newly;
            any |= newly;
            if (newly) {
                uint32_t* dp = (uint32_t*)(drow + w * 32);
#pragma unroll
                for (int q = 0; q < 8; ++q) {
                    uint32_t nib = (newly >> (q * 4)) & 0xF;
                    if (nib) {
                        uint32_t m = ((nib & 1) ? 0xFFu : 0u) | ((nib & 2) ? 0xFF00u : 0u)
                                   | ((nib & 4) ? 0xFF0000u : 0u) | ((nib & 8) ? 0xFF000000u : 0u);
                        dp[q] = (dp[q] & ~m) | (rep & m);
                    }
                }
            }
        }
        if (!any) break;
    }
}

// ---------------- bf16x3 tensor-core GEMM ----------------
#define CP16(dst, src) asm volatile("cp.async.cg.shared.global [%0], [%1], 16;\n" :: "r"(dst), "l"(src))
#define MMA16816(d, a0, a1, a2, a3, b0, b1) \
    asm volatile("mma.sync.aligned.m16n8k16.row.col.f32.bf16.bf16.f32 " \
                 "{%0,%1,%2,%3}, {%4,%5,%6,%7}, {%8,%9}, {%0,%1,%2,%3};" \
                 : "+f"(d[0]), "+f"(d[1]), "+f"(d[2]), "+f"(d[3]) \
                 : "r"(a0), "r"(a1), "r"(a2), "r"(a3), "r"(b0), "r"(b1))

template <int GELU, int RES, int OUTBF16>
__launch_bounds__(256)
__global__ void gemm_bf16(const __nv_bfloat16* __restrict__ Ahi, const __nv_bfloat16* __restrict__ Alo,
                          const __nv_bfloat16* __restrict__ Whi, const __nv_bfloat16* __restrict__ Wlo,
                          const float* __restrict__ bias, const float* __restrict__ res,
                          float* __restrict__ C, __nv_bfloat16* __restrict__ Chi,
                          __nv_bfloat16* __restrict__ Clo, int K, int F) {
    extern __shared__ unsigned char smp[];
    const int STG = 40960;
    int m0 = blockIdx.x * 128, f0 = blockIdx.y * 128;
    int tid = threadIdx.x, lane = tid & 31, warp = tid >> 5;
    int g = lane >> 2, tg = lane & 3;
    int wm = (warp >> 2) * 64, wn = (warp & 3) * 32;
    uint32_t smem_base = (uint32_t)__cvta_generic_to_shared(smp);

    float acc[4][4][4];
#pragma unroll
    for (int a = 0; a < 4; ++a)
#pragma unroll
        for (int b = 0; b < 4; ++b)
#pragma unroll
            for (int c = 0; c < 4; ++c) acc[a][b][c] = 0.f;

    auto load_stage = [&](int s, int k0) {
        uint32_t db = smem_base + s * STG;
        const __nv_bfloat16* srcs[4] = {
            Ahi + (size_t)m0 * K + k0, Alo + (size_t)m0 * K + k0,
            Whi + (size_t)f0 * K + k0, Wlo + (size_t)f0 * K + k0 };
#pragma unroll
        for (int arr = 0; arr < 4; ++arr) {
            const __nv_bfloat16* bp = srcs[arr];
            uint32_t ab = db + arr * 10240;
#pragma unroll
            for (int c = 0; c < 2; ++c) {
                int t = tid + c * 256;
                int row = t >> 2, ch = t & 3;
                CP16(ab + row * 80 + ch * 16, bp + (size_t)row * K + ch * 8);
            }
        }
        asm volatile("cp.async.commit_group;\n" ::);
    };

    int nk = K >> 5;
    load_stage(0, 0);
    for (int kc = 0; kc < nk; ++kc) {
        if (kc + 1 < nk) {
            load_stage((kc + 1) & 1, (kc + 1) << 5);
            asm volatile("cp.async.wait_group 1;\n" ::);
        } else {
            asm volatile("cp.async.wait_group 0;\n" ::);
        }
        __syncthreads();

        const uint32_t* Ah = (const uint32_t*)(smp + (kc & 1) * STG);
        const uint32_t* Al = Ah + 2560;
        const uint32_t* Wh = Ah + 5120;
        const uint32_t* Wl = Ah + 7680;
#pragma unroll
        for (int ks = 0; ks < 2; ++ks) {
            int ku = ks * 8;
            uint32_t bh[4][2], bl[4][2];
#pragma unroll
            for (int nt = 0; nt < 4; ++nt) {
                int idx = (wn + nt * 8 + g) * 20 + ku + tg;
                bh[nt][0] = Wh[idx]; bh[nt][1] = Wh[idx + 4];
                bl[nt][0] = Wl[idx]; bl[nt][1] = Wl[idx + 4];
            }
#pragma unroll
            for (int mt = 0; mt < 4; ++mt) {
                int i0 = (wm + mt * 16 + g) * 20 + ku + tg;
                int i1 = i0 + 160;
                uint32_t ah0 = Ah[i0], ah1 = Ah[i1], ah2 = Ah[i0 + 4], ah3 = Ah[i1 + 4];
                uint32_t al0 = Al[i0], al1 = Al[i1], al2 = Al[i0 + 4], al3 = Al[i1 + 4];
#pragma unroll
                for (int nt = 0; nt < 4; ++nt) {
                    MMA16816(acc[mt][nt], ah0, ah1, ah2, ah3, bh[nt][0], bh[nt][1]);
                    MMA16816(acc[mt][nt], ah0, ah1, ah2, ah3, bl[nt][0], bl[nt][1]);
                    MMA16816(acc[mt][nt], al0, al1, al2, al3, bh[nt][0], bh[nt][1]);
                }
            }
        }
        __syncthreads();
    }

#pragma unroll
    for (int mt = 0; mt < 4; ++mt) {
#pragma unroll
        for (int half = 0; half < 2; ++half) {
            int row = m0 + wm + mt * 16 + g + half * 8;
#pragma unroll
            for (int nt = 0; nt < 4; ++nt) {
                int col = f0 + wn + nt * 8 + tg * 2;
                float v0 = acc[mt][nt][half * 2 + 0];
                float v1 = acc[mt][nt][half * 2 + 1];
                if (bias) { v0 += bias[col]; v1 += bias[col + 1]; }
                if (GELU) { v0 = v0 * normcdff(v0); v1 = v1 * normcdff(v1); }
                if (RES)  { v0 += res[(size_t)row * F + col]; v1 += res[(size_t)row * F + col + 1]; }
                if (OUTBF16) {
                    uint32_t h, l;
                    split2(v0, v1, h, l);
                    *(uint32_t*)(Chi + (size_t)row * F + col) = h;
                    *(uint32_t*)(Clo + (size_t)row * F + col) = l;
                } else {
                    float2 o; o.x = v0; o.y = v1;
                    *(float2*)(C + (size_t)row * F + col) = o;
                }
            }
        }
    }
}

// ---------------- qkv prepass: split q(prescaled)/k, transpose v ----------------
__launch_bounds__(256)
__global__ void qkv_prep(const float* __restrict__ qkv,
                         __nv_bfloat16* __restrict__ qh, __nv_bfloat16* __restrict__ ql,
                         __nv_bfloat16* __restrict__ kh, __nv_bfloat16* __restrict__ kl,
                         __nv_bfloat16* __restrict__ vth, __nv_bfloat16* __restrict__ vtl) {
    __shared__ float vsm[64][33];
    int nb = blockIdx.x * 64;           // 64 nodes per block, all in same graph
    int g = nb >> 10;
    int jb = nb & 1023;
    int tid = threadIdx.x;
    const float scale = 0.17677669529663687f;   // HD^-0.5

    // q/k: 64 rows x 128 f4
#pragma unroll
    for (int it = 0; it < 32; ++it) {
        int flat = tid + it * 256;
        int row = flat >> 7, c4 = flat & 127;
        int node = nb + row;
        float4 v = *(const float4*)&qkv[(size_t)node * QKVD + c4 * 4];
        int c = c4 * 4;
        uint32_t h0, l0, h1, l1;
        if (c < 256) {
            split2(v.x * scale, v.y * scale, h0, l0);
            split2(v.z * scale, v.w * scale, h1, l1);
            *(uint2*)(qh + (size_t)node * HH + c) = make_uint2(h0, h1);
            *(uint2*)(ql + (size_t)node * HH + c) = make_uint2(l0, l1);
        } else {
            split2(v.x, v.y, h0, l0);
            split2(v.z, v.w, h1, l1);
            *(uint2*)(kh + (size_t)node * HH + c - 256) = make_uint2(h0, h1);
            *(uint2*)(kl + (size_t)node * HH + c - 256) = make_uint2(l0, l1);
        }
    }

    // v transpose per head
    for (int h = 0; h < NHEADS; ++h) {
        __syncthreads();
#pragma unroll
        for (int it = 0; it < 2; ++it) {
            int flat = tid + it * 256;     // 64 rows x 8 f4
            int row = flat >> 3, c4 = flat & 7;
            float4 v = *(const float4*)&qkv[(size_t)(nb + row) * QKVD + 512 + h * 32 + c4 * 4];
            vsm[row][c4 * 4 + 0] = v.x;
            vsm[row][c4 * 4 + 1] = v.y;
            vsm[row][c4 * 4 + 2] = v.z;
            vsm[row][c4 * 4 + 3] = v.w;
        }
        __syncthreads();
        int d = tid >> 3, j0 = (tid & 7) * 8;
        uint32_t hw[4], lw[4];
#pragma unroll
        for (int p = 0; p < 4; ++p) {
            float a = vsm[j0 + p * 2 + 0][d];
            float b = vsm[j0 + p * 2 + 1][d];
            split2(a, b, hw[p], lw[p]);
        }
        size_t off = ((size_t)(g * NHEADS + h) * HDIM + d) * MM + jb + j0;
        *(uint4*)(vth + off) = make_uint4(hw[0], hw[1], hw[2], hw[3]);
        *(uint4*)(vtl + off) = make_uint4(lw[0], lw[1], lw[2], lw[3]);
    }
}

// ---------------- tensor-core flash attention ----------------
// grid (64 gh, 8 qblocks), 256 threads (8 warps x 16 query rows)
__launch_bounds__(256)
__global__ void attn_mma(const __nv_bfloat16* __restrict__ qh, const __nv_bfloat16* __restrict__ ql,
                         const __nv_bfloat16* __restrict__ kh, const __nv_bfloat16* __restrict__ kl,
                         const __nv_bfloat16* __restrict__ vth, const __nv_bfloat16* __restrict__ vtl,
                         const unsigned char* __restrict__ dist, const float* __restrict__ bias_emb,
                         __nv_bfloat16* __restrict__ ohi, __nv_bfloat16* __restrict__ olo) {
    extern __shared__ unsigned char smp[];
    const int STG = 37888;   // KH 10240 + KL 10240 + VTH 8704 + VTL 8704
    __shared__ float btab[8];
    int gh = blockIdx.x;
    int g = gh >> 3, h = gh & 7;
    int i0 = blockIdx.y * 128;
    int tid = threadIdx.x, lane = tid & 31, warp = tid >> 5;
    int r = lane >> 2, tg = lane & 3;
    if (tid < 7) btab[tid] = bias_emb[tid];
    uint32_t sb = (uint32_t)__cvta_generic_to_shared(smp);
    const float L2E = 1.44269504f;

    // Q fragments (loaded once)
    int rowA = i0 + warp * 16 + r;
    int rowB = rowA + 8;
    uint32_t qfh[2][4], qfl[2][4];
#pragma unroll
    for (int kc = 0; kc < 2; ++kc) {
        size_t baseA = (size_t)(g * MM + rowA) * HH + h * HDIM + kc * 16 + tg * 2;
        size_t baseB = (size_t)(g * MM + rowB) * HH + h * HDIM + kc * 16 + tg * 2;
        qfh[kc][0] = *(const uint32_t*)(qh + baseA);
        qfh[kc][1] = *(const uint32_t*)(qh + baseB);
        qfh[kc][2] = *(const uint32_t*)(qh + baseA + 8);
        qfh[kc][3] = *(const uint32_t*)(qh + baseB + 8);
        qfl[kc][0] = *(const uint32_t*)(ql + baseA);
        qfl[kc][1] = *(const uint32_t*)(ql + baseB);
        qfl[kc][2] = *(const uint32_t*)(ql + baseA + 8);
        qfl[kc][3] = *(const uint32_t*)(ql + baseB + 8);
    }

    float acc_o[4][4];
#pragma unroll
    for (int a = 0; a < 4; ++a)
#pragma unroll
        for (int b = 0; b < 4; ++b) acc_o[a][b] = 0.f;
    float mA = -1e30f, mB = -1e30f, lA = 0.f, lB = 0.f;

    const unsigned char* drowA = dist + ((size_t)(g * MM + rowA)) * MM;
    const unsigned char* drowB = dist + ((size_t)(g * MM + rowB)) * MM;

    auto load_stage = [&](int s, int j0) {
        uint32_t db = sb + s * STG;
        // K hi/lo: 128 rows x 64B (pad to 80B)
#pragma unroll
        for (int c = 0; c < 2; ++c) {
            int t = tid + c * 256;
            int row = t >> 2, ch = t & 3;
            const __nv_bfloat16* src = kh + (size_t)(g * MM + j0 + row) * HH + h * HDIM + ch * 8;
            CP16(db + row * 80 + ch * 16, src);
            const __nv_bfloat16* srcl = kl + (size_t)(g * MM + j0 + row) * HH + h * HDIM + ch * 8;
            CP16(db + 10240 + row * 80 + ch * 16, srcl);
        }
        // VT hi/lo: 32 rows x 256B (pad to 272B)
#pragma unroll
        for (int c = 0; c < 2; ++c) {
            int t = tid + c * 256;
            int row = t >> 4, ch = t & 15;
            size_t off = ((size_t)(gh) * HDIM + row) * MM + j0 + ch * 8;
            CP16(db + 20480 + row * 272 + ch * 16, vth + off);
            CP16(db + 29184 + row * 272 + ch * 16, vtl + off);
        }
        asm volatile("cp.async.commit_group;\n" ::);
    };

    load_stage(0, 0);
    for (int ch = 0; ch < 8; ++ch) {
        int j0 = ch * 128;
        if (ch < 7) {
            load_stage((ch + 1) & 1, j0 + 128);
            asm volatile("cp.async.wait_group 1;\n" ::);
        } else {
            asm volatile("cp.async.wait_group 0;\n" ::);
        }
        __syncthreads();

        const uint32_t* KH = (const uint32_t*)(smp + (ch & 1) * STG);
        const uint32_t* KL = KH + 2560;
        const uint32_t* VH = KH + 5120;
        const uint32_t* VL = VH + 2176;

        // S = Q·K^T (3-term)
        float acc_s[16][4];
#pragma unroll
        for (int nt = 0; nt < 16; ++nt)
#pragma unroll
            for (int c = 0; c < 4; ++c) acc_s[nt][c] = 0.f;
#pragma unroll
        for (int kc = 0; kc < 2; ++kc) {
#pragma unroll
            for (int nt = 0; nt < 16; ++nt) {
                int idx = (nt * 8 + r) * 20 + kc * 8 + tg;
                uint32_t b0h = KH[idx], b1h = KH[idx + 4];
                uint32_t b0l = KL[idx], b1l = KL[idx + 4];
                MMA16816(acc_s[nt], qfh[kc][0], qfh[kc][1], qfh[kc][2], qfh[kc][3], b0h, b1h);
                MMA16816(acc_s[nt], qfh[kc][0], qfh[kc][1], qfh[kc][2], qfh[kc][3], b0l, b1l);
                MMA16816(acc_s[nt], qfl[kc][0], qfl[kc][1], qfl[kc][2], qfl[kc][3], b0h, b1h);
            }
        }

        // bias + row max
        float cmA = -1e30f, cmB = -1e30f;
#pragma unroll
        for (int nt = 0; nt < 16; ++nt) {
            uchar2 dA = *(const uchar2*)(drowA + j0 + nt * 8 + tg * 2);
            uchar2 dB = *(const uchar2*)(drowB + j0 + nt * 8 + tg * 2);
            acc_s[nt][0] += btab[dA.x];
            acc_s[nt][1] += btab[dA.y];
            acc_s[nt][2] += btab[dB.x];
            acc_s[nt][3] += btab[dB.y];
            cmA = fmaxf(cmA, fmaxf(acc_s[nt][0], acc_s[nt][1]));
            cmB = fmaxf(cmB, fmaxf(acc_s[nt][2], acc_s[nt][3]));
        }
        cmA = fmaxf(cmA, __shfl_xor_sync(0xFFFFFFFFu, cmA, 1));
        cmA = fmaxf(cmA, __shfl_xor_sync(0xFFFFFFFFu, cmA, 2));
        cmB = fmaxf(cmB, __shfl_xor_sync(0xFFFFFFFFu, cmB, 1));
        cmB = fmaxf(cmB, __shfl_xor_sync(0xFFFFFFFFu, cmB, 2));

        float mAn = fmaxf(mA, cmA), mBn = fmaxf(mB, cmB);
        float corrA = ex2f((mA - mAn) * L2E);
        float corrB = ex2f((mB - mBn) * L2E);
        mA = mAn; mB = mBn;

        // exp + pack P hi/lo
        uint32_t ph0[16], ph1[16], pl0[16], pl1[16];
        float lsA = 0.f, lsB = 0.f;
#pragma unroll
        for (int nt = 0; nt < 16; ++nt) {
            float p0 = ex2f((acc_s[nt][0] - mA) * L2E);
            float p1 = ex2f((acc_s[nt][1] - mA) * L2E);
            float p2 = ex2f((acc_s[nt][2] - mB) * L2E);
            float p3 = ex2f((acc_s[nt][3] - mB) * L2E);
            lsA += p0 + p1; lsB += p2 + p3;
            split2(p0, p1, ph0[nt], pl0[nt]);
            split2(p2, p3, ph1[nt], pl1[nt]);
        }
        lsA += __shfl_xor_sync(0xFFFFFFFFu, lsA, 1);
        lsA += __shfl_xor_sync(0xFFFFFFFFu, lsA, 2);
        lsB += __shfl_xor_sync(0xFFFFFFFFu, lsB, 1);
        lsB += __shfl_xor_sync(0xFFFFFFFFu, lsB, 2);
        lA = lA * corrA + lsA;
        lB = lB * corrB + lsB;

#pragma unroll
        for (int nto = 0; nto < 4; ++nto) {
            acc_o[nto][0] *= corrA; acc_o[nto][1] *= corrA;
            acc_o[nto][2] *= corrB; acc_o[nto][3] *= corrB;
        }

        // O += P·V (3-term)
#pragma unroll
        for (int kc = 0; kc < 8; ++kc) {
            uint32_t a0 = ph0[2 * kc], a1 = ph1[2 * kc], a2 = ph0[2 * kc + 1], a3 = ph1[2 * kc + 1];
            uint32_t c0 = pl0[2 * kc], c1 = pl1[2 * kc], c2 = pl0[2 * kc + 1], c3 = pl1[2 * kc + 1];
#pragma unroll
            for (int nto = 0; nto < 4; ++nto) {
                int idx = (nto * 8 + r) * 68 + kc * 8 + tg;
                uint32_t b0h = VH[idx], b1h = VH[idx + 4];
                uint32_t b0l = VL[idx], b1l = VL[idx + 4];
                MMA16816(acc_o[nto], a0, a1, a2, a3, b0h, b1h);
                MMA16816(acc_o[nto], a0, a1, a2, a3, b0l, b1l);
                MMA16816(acc_o[nto], c0, c1, c2, c3, b0h, b1h);
            }
        }
        __syncthreads();
    }

    // epilogue: normalize + bf16 split stores
    float invA = 1.f / lA, invB = 1.f / lB;
#pragma unroll
    for (int nto = 0; nto < 4; ++nto) {
        int col = h * HDIM + nto * 8 + tg * 2;
        float a0 = acc_o[nto][0] * invA, a1 = acc_o[nto][1] * invA;
        float b0 = acc_o[nto][2] * invB, b1 = acc_o[nto][3] * invB;
        uint32_t hA, lA2, hB, lB2;
        split2(a0, a1, hA, lA2);
        split2(b0, b1, hB, lB2);
        *(uint32_t*)(ohi + (size_t)(g * MM + rowA) * HH + col) = hA;
        *(uint32_t*)(olo + (size_t)(g * MM + rowA) * HH + col) = lA2;
        *(uint32_t*)(ohi + (size_t)(g * MM + rowB) * HH + col) = hB;
        *(uint32_t*)(olo + (size_t)(g * MM + rowB) * HH + col) = lB2;
    }
}

// ---------------- LayerNorm (up to 3 summed inputs) ----------------
__launch_bounds__(256)
__global__ void ln_kernel(const float* __restrict__ a, const float* __restrict__ b,
                          const float* __restrict__ c, const float* __restrict__ gam,
                          const float* __restrict__ bet, float* __restrict__ out,
                          __nv_bfloat16* __restrict__ ohi, __nv_bfloat16* __restrict__ olo) {
    int row = blockIdx.x, t = threadIdx.x;
    size_t idx = (size_t)row * HH + t;
    float v = a[idx];
    if (b) v += b[idx];
    if (c) v += c[idx];
    float s = v, s2 = v * v;
#pragma unroll
    for (int o = 16; o; o >>= 1) {
        s  += __shfl_xor_sync(0xFFFFFFFFu, s, o);
        s2 += __shfl_xor_sync(0xFFFFFFFFu, s2, o);
    }
    __shared__ float sh1[8], sh2[8];
    int w = t >> 5, ln = t & 31;
    if (ln == 0) { sh1[w] = s; sh2[w] = s2; }
    __syncthreads();
    if (w == 0) {
        s  = (ln < 8) ? sh1[ln] : 0.f;
        s2 = (ln < 8) ? sh2[ln] : 0.f;
#pragma unroll
        for (int o = 4; o; o >>= 1) {
            s  += __shfl_xor_sync(0xFFFFFFFFu, s, o);
            s2 += __shfl_xor_sync(0xFFFFFFFFu, s2, o);
        }
        if (ln == 0) { sh1[0] = s; sh2[0] = s2; }
    }
    __syncthreads();
    float mean = sh1[0] * (1.f / HH);
    float var  = sh2[0] * (1.f / HH) - mean * mean;
    float rr = (v - mean) * rsqrtf(var + 1e-5f) * gam[t] + bet[t];
    out[idx] = rr;
    if (ohi) {
        __nv_bfloat16 hh = __float2bfloat16(rr);
        ohi[idx] = hh;
        olo[idx] = __float2bfloat16(rr - __bfloat162float(hh));
    }
}

// ---------------- host ----------------
static void* sym(const void* s) { void* p = nullptr; cudaGetSymbolAddress(&p, s); return p; }

extern "C" void kernel_launch(void* const* d_in, const int* in_sizes, int n_in,
                              void* d_out, int out_size) {
    const float* x      = (const float*)d_in[0];
    const float* gcn_w  = (const float*)d_in[1];
    const float* gcn_b  = (const float*)d_in[2];
    const float* qkv_w  = (const float*)d_in[3];
    const float* qkv_b  = (const float*)d_in[4];
    const float* proj_w = (const float*)d_in[5];
    const float* proj_b = (const float*)d_in[6];
    const float* ln1_g  = (const float*)d_in[7];
    const float* ln1_b  = (const float*)d_in[8];
    const float* ln2_g  = (const float*)d_in[9];
    const float* ln2_b  = (const float*)d_in[10];
    const float* ffn1_w = (const float*)d_in[11];
    const float* ffn1_b = (const float*)d_in[12];
    const float* ffn2_w = (const float*)d_in[13];
    const float* ffn2_b = (const float*)d_in[14];
    const float* bias_e = (const float*)d_in[15];
    const float* oln1_g = (const float*)d_in[16];
    const float* oln1_b = (const float*)d_in[17];
    const float* oln2_g = (const float*)d_in[18];
    const float* oln2_b = (const float*)d_in[19];
    const float* offn1_w= (const float*)d_in[20];
    const float* offn1_b= (const float*)d_in[21];
    const float* offn2_w= (const float*)d_in[22];
    const float* offn2_b= (const float*)d_in[23];
    const int*   ei     = (const int*)d_in[24];
    int E = in_sizes[24] / 2;

    float*    p_deg  = (float*)sym(g_deg);
    float*    p_dinv = (float*)sym(g_dinv);
    float*    p_xw   = (float*)sym(g_xw);
    float*    p_xl   = (float*)sym(g_xl);
    uint32_t* p_adj  = (uint32_t*)sym(g_adj);
    unsigned char* p_dist = (unsigned char*)sym(g_dist);
    float*    p_qkv  = (float*)sym(g_qkv);
    float*    p_tmp  = (float*)sym(g_tmp);
    float*    p_h1   = (float*)sym(g_h1);
    float*    p_h2   = (float*)sym(g_h2);
    float*    p_y    = (float*)sym(g_y);
    __nv_bfloat16* x_hi  = (__nv_bfloat16*)sym(g_x_hi);
    __nv_bfloat16* x_lo  = (__nv_bfloat16*)sym(g_x_lo);
    __nv_bfloat16* at_hi = (__nv_bfloat16*)sym(g_at_hi);
    __nv_bfloat16* at_lo = (__nv_bfloat16*)sym(g_at_lo);
    __nv_bfloat16* h1_hi = (__nv_bfloat16*)sym(g_h1_hi);
    __nv_bfloat16* h1_lo = (__nv_bfloat16*)sym(g_h1_lo);
    __nv_bfloat16* y_hi  = (__nv_bfloat16*)sym(g_y_hi);
    __nv_bfloat16* y_lo  = (__nv_bfloat16*)sym(g_y_lo);
    __nv_bfloat16* mid_hi= (__nv_bfloat16*)sym(g_mid_hi);
    __nv_bfloat16* mid_lo= (__nv_bfloat16*)sym(g_mid_lo);
    __nv_bfloat16* q_hi  = (__nv_bfloat16*)sym(g_q_hi);
    __nv_bfloat16* q_lo  = (__nv_bfloat16*)sym(g_q_lo);
    __nv_bfloat16* k_hi  = (__nv_bfloat16*)sym(g_k_hi);
    __nv_bfloat16* k_lo  = (__nv_bfloat16*)sym(g_k_lo);
    __nv_bfloat16* vt_hi = (__nv_bfloat16*)sym(g_vt_hi);
    __nv_bfloat16* vt_lo = (__nv_bfloat16*)sym(g_vt_lo);
    __nv_bfloat16* whi   = (__nv_bfloat16*)sym(g_whi);
    __nv_bfloat16* wlo   = (__nv_bfloat16*)sym(g_wlo);
    float* out = (float*)d_out;

    const int SMEM = 81920;
    const int ASMEM = 75776;
    cudaFuncSetAttribute(gemm_bf16<0,0,0>, cudaFuncAttributeMaxDynamicSharedMemorySize, SMEM);
    cudaFuncSetAttribute(gemm_bf16<0,1,0>, cudaFuncAttributeMaxDynamicSharedMemorySize, SMEM);
    cudaFuncSetAttribute(gemm_bf16<1,0,1>, cudaFuncAttributeMaxDynamicSharedMemorySize, SMEM);
    cudaFuncSetAttribute(attn_mma, cudaFuncAttributeMaxDynamicSharedMemorySize, ASMEM);
    cudaFuncSetAttribute(spd_kernel, cudaFuncAttributeMaxDynamicSharedMemorySize, MM * 33 * 4);

    // --- splits ---
    split4<<<(NN * HH / 4 + 255) / 256, 256>>>((const float4*)x, x_hi, x_lo, NN * HH / 4);
    splitw<<<(344064 + 255) / 256, 256>>>((const float4*)gcn_w, (const float4*)qkv_w,
        (const float4*)proj_w, (const float4*)ffn1_w, (const float4*)ffn2_w,
        (const float4*)offn1_w, (const float4*)offn2_w, whi, wlo);

    // --- graph prep ---
    zero_prep<<<(GG * MM * 32 + 255) / 256, 256>>>(p_deg, p_adj);
    edge_prep<<<(E + 255) / 256, 256>>>(ei, E, p_deg, p_adj);
    dinv_kernel<<<NN / 256, 256>>>(p_deg, p_dinv);
    gemm_bf16<0,0,0><<<dim3(NN/128, HH/128), 256, SMEM>>>(x_hi, x_lo, whi + OFF_GCN, wlo + OFF_GCN,
        nullptr, nullptr, p_xw, nullptr, nullptr, HH, HH);
    xlocal_init<<<NN * HH / 256, 256>>>(p_xw, p_dinv, gcn_b, p_xl);
    edge_scatter<<<(E * 64 + 255) / 256, 256>>>(ei, E, p_xw, p_dinv, p_xl);
    spd_kernel<<<64, 128, MM * 33 * 4>>>(p_adj, p_dist);

    // --- Graphormer layer ---
    gemm_bf16<0,0,0><<<dim3(NN/128, QKVD/128), 256, SMEM>>>(x_hi, x_lo, whi + OFF_QKV, wlo + OFF_QKV,
        qkv_b, nullptr, p_qkv, nullptr, nullptr, HH, QKVD);
    qkv_prep<<<NN / 64, 256>>>(p_qkv, q_hi, q_lo, k_hi, k_lo, vt_hi, vt_lo);
    attn_mma<<<dim3(GG * NHEADS, MM / 128), 256, ASMEM>>>(q_hi, q_lo, k_hi, k_lo, vt_hi, vt_lo,
        p_dist, bias_e, at_hi, at_lo);
    gemm_bf16<0,1,0><<<dim3(NN/128, HH/128), 256, SMEM>>>(at_hi, at_lo, whi + OFF_PROJ, wlo + OFF_PROJ,
        proj_b, x, p_tmp, nullptr, nullptr, HH, HH);
    ln_kernel<<<NN, 256>>>(p_tmp, nullptr, nullptr, ln1_g, ln1_b, p_h1, h1_hi, h1_lo);
    gemm_bf16<1,0,1><<<dim3(NN/128, FFND/128), 256, SMEM>>>(h1_hi, h1_lo, whi + OFF_FFN1, wlo + OFF_FFN1,
        ffn1_b, nullptr, nullptr, mid_hi, mid_lo, HH, FFND);
    gemm_bf16<0,1,0><<<dim3(NN/128, HH/128), 256, SMEM>>>(mid_hi, mid_lo, whi + OFF_FFN2, wlo + OFF_FFN2,
        ffn2_b, p_h1, p_tmp, nullptr, nullptr, FFND, HH);
    ln_kernel<<<NN, 256>>>(p_tmp, nullptr, nullptr, ln2_g, ln2_b, p_h2, nullptr, nullptr);

    // --- GPS combine + outer FFN ---
    ln_kernel<<<NN, 256>>>(x, p_xl, p_h2, oln1_g, oln1_b, p_y, y_hi, y_lo);
    gemm_bf16<1,0,1><<<dim3(NN/128, FFND/128), 256, SMEM>>>(y_hi, y_lo, whi + OFF_OFFN1, wlo + OFF_OFFN1,
        offn1_b, nullptr, nullptr, mid_hi, mid_lo, HH, FFND);
    gemm_bf16<0,1,0><<<dim3(NN/128, HH/128), 256, SMEM>>>(mid_hi, mid_lo, whi + OFF_OFFN2, wlo + OFF_OFFN2,
        offn2_b, p_y, p_tmp, nullptr, nullptr, FFND, HH);
    ln_kernel<<<NN, 256>>>(p_tmp, nullptr, nullptr, oln2_g, oln2_b, out, nullptr, nullptr);
}